// round 12
// baseline (speedup 1.0000x reference)
#include <cuda_runtime.h>

#define B_ROWS 16384
#define NQUADS (B_ROWS / 4)      // 4096 row-quads
#define NN     128
#define NS     1024
#define GRID_MAIN 296            // 2 blocks/SM * 148 SMs
#define BLOCK_MAIN 256
#define NSHARD 4

#define C_LOG2E  1.4426950408889634f
#define C_LN2    0.6931471805599453f

// ---------------- scratch (device globals; statically zero-initialized) ----------------
// Invariant: zero at entry of every kernel_launch; finalizing block resets.
__device__ float g_sA[NSHARD][NS];   // sum g*s*softplus(-x)  (sub, pw-weighted part)
__device__ float g_sC[NSHARD][NS];   // sum s (ungated column count)
__device__ float g_nU[NSHARD][NN];   // sum y*softplus(-x)    (narrative)
__device__ float g_nC[NSHARD][NN];   // sum y
__device__ float g_scl[8];           // 0=Qs 1=Wn 2=hier 3=nf 4=sf
__device__ unsigned int g_ctr;

__device__ __forceinline__ float softplus_f(float x) {
    // softplus(x) = max(x,0) + log1p(exp(-|x|)); EX2 + LG2
    float e = exp2f(-C_LOG2E * fabsf(x));
    float L = __log2f(1.0f + e);
    return fmaxf(x, 0.0f) + C_LN2 * L;
}

__global__ __launch_bounds__(BLOCK_MAIN, 2)
void fused_kernel(const float* __restrict__ nlg, const float* __restrict__ slg,
                  const int* __restrict__ nlb,  const int* __restrict__ slb,
                  float* __restrict__ out)
{
    const int tid = threadIdx.x;
    const int bid = blockIdx.x;
    const int par = tid & 1;                 // 0: narrative rows {0,2}; 1: rows {1,3}
    const int c   = tid >> 1;                // narrative class for this thread

    float A[4]  = {0.f, 0.f, 0.f, 0.f};
    float cs[4] = {0.f, 0.f, 0.f, 0.f};
    float Un = 0.f, cnf = 0.f, Qs = 0.f, Wn = 0.f, hier = 0.f, nfp = 0.f, sfp = 0.f;

    // quad q -> rows (4q .. 4q+3); warp = 512B contiguous per vector load
    const float4* sp  = (const float4*)slg + (size_t)bid * 4 * (NS / 4) + tid;
    const int4*   slp = (const int4*)slb   + (size_t)bid * 4 * (NS / 4) + tid;
    const float*  np  = nlg + ((size_t)bid * 4 + par) * NN + c;   // rows par, par+2
    const int*    nbp = nlb + ((size_t)bid * 4 + par) * NN + c;
    const size_t  sstep = (size_t)GRID_MAIN * 4 * (NS / 4);
    const size_t  nstep = (size_t)GRID_MAIN * 4 * NN;
    const int     ROWQ = NS / 4;  // float4s per row

    for (int qd = bid; qd < NQUADS; qd += GRID_MAIN) {
        // ---- 12 independent loads, front-batched by compiler (high MLP) ----
        float4 v0 = __ldcs(sp),            v1 = __ldcs(sp + ROWQ);
        float4 v2 = __ldcs(sp + 2 * ROWQ), v3 = __ldcs(sp + 3 * ROWQ);
        int4   l0 = __ldcs(slp),            l1 = __ldcs(slp + ROWQ);
        int4   l2 = __ldcs(slp + 2 * ROWQ), l3 = __ldcs(slp + 3 * ROWQ);
        float  xn0 = __ldcs(np),  xn1 = __ldcs(np + 2 * NN);
        int    gi0 = __ldcs(nbp), gi1 = __ldcs(nbp + 2 * NN);
        sp += sstep; slp += sstep; np += nstep; nbp += nstep;

        // ---- 2 narrative elements (own rows par, par+2) ----
        float g0 = (float)gi0, g1 = (float)gi1;
        float pn0, pn1;
        {
            float e0 = exp2f(-C_LOG2E * fabsf(xn0));
            float t0 = 1.0f + e0;
            float q0 = __fdividef(1.0f, t0);
            float spn0 = fmaxf(xn0, 0.0f) + C_LN2 * __log2f(t0);
            float spm0 = spn0 - xn0;
            bool  pos0 = (xn0 >= 0.0f);
            pn0 = pos0 ? q0 : e0 * q0;
            float om0 = pos0 ? e0 * q0 : q0;
            nfp = fmaf(g0 * om0 * om0, spm0, nfp);
            Un  = fmaf(g0, spm0, Un);
            Wn  = fmaf(1.0f - g0, spn0, Wn);

            float e1 = exp2f(-C_LOG2E * fabsf(xn1));
            float t1 = 1.0f + e1;
            float q1 = __fdividef(1.0f, t1);
            float spn1 = fmaxf(xn1, 0.0f) + C_LN2 * __log2f(t1);
            float spm1 = spn1 - xn1;
            bool  pos1 = (xn1 >= 0.0f);
            pn1 = pos1 ? q1 : e1 * q1;
            float om1 = pos1 ? e1 * q1 : q1;
            nfp = fmaf(g1 * om1 * om1, spm1, nfp);
            Un  = fmaf(g1, spm1, Un);
            Wn  = fmaf(1.0f - g1, spn1, Wn);
            cnf += g0 + g1;
        }

        // ---- exchange gates across the thread pair (packed, 1 shfl) ----
        int   pk   = gi0 | (gi1 << 1);
        int   pko  = __shfl_xor_sync(0xffffffffu, pk, 1);
        float og0  = (float)(pko & 1);        // other's first row gate
        float og1  = (float)((pko >> 1) & 1); // other's second row gate
        // gates for rows 0..3 of class c
        float gr0 = par ? og0 : g0;
        float gr1 = par ? g0  : og0;
        float gr2 = par ? og1 : g1;
        float gr3 = par ? g1  : og1;

        // ---- 16 sub elements: 4 rows x 4 cols ----
        float xr[4][4] = { { v0.x, v0.y, v0.z, v0.w }, { v1.x, v1.y, v1.z, v1.w },
                           { v2.x, v2.y, v2.z, v2.w }, { v3.x, v3.y, v3.z, v3.w } };
        int   lr[4][4] = { { l0.x, l0.y, l0.z, l0.w }, { l1.x, l1.y, l1.z, l1.w },
                           { l2.x, l2.y, l2.z, l2.w }, { l3.x, l3.y, l3.z, l3.w } };
        float gr[4] = { gr0, gr1, gr2, gr3 };
        float mx[4];
#pragma unroll
        for (int rr = 0; rr < 4; rr++) {
            float m = xr[rr][0];
            float grr = gr[rr];
#pragma unroll
            for (int k = 0; k < 4; k++) {
                float x   = xr[rr][k];
                float s   = __int_as_float(lr[rr][k] * 0x3f800000);
                float spx = softplus_f(x);
                float spm = spx - x;
                float w   = exp2f(-2.0f * C_LOG2E * spx);
                sfp = fmaf(s * w, spm, sfp);
                float gs = grr * s;
                A[k] = fmaf(gs, spm, A[k]);
                Qs   = fmaf(grr - gs, spx, Qs);
                cs[k] += s;
                m = fmaxf(m, x);
            }
            mx[rr] = m;
        }

        // ---- hierarchy: full class max per row via pair shfl; own rows only ----
        float f0 = fmaxf(mx[0], __shfl_xor_sync(0xffffffffu, mx[0], 1));
        float f1 = fmaxf(mx[1], __shfl_xor_sync(0xffffffffu, mx[1], 1));
        float f2 = fmaxf(mx[2], __shfl_xor_sync(0xffffffffu, mx[2], 1));
        float f3 = fmaxf(mx[3], __shfl_xor_sync(0xffffffffu, mx[3], 1));
        float fa = par ? f1 : f0;   // full max for own first row
        float fb = par ? f3 : f2;   // full max for own second row
        {
            float ea = exp2f(-C_LOG2E * fa);
            float pa = __fdividef(1.0f, 1.0f + ea);
            hier = fmaf(g0, fmaxf(pa - pn0, 0.0f), hier);
            float eb = exp2f(-C_LOG2E * fb);
            float pb = __fdividef(1.0f, 1.0f + eb);
            hier = fmaf(g1, fmaxf(pb - pn1, 0.0f), hier);
        }
    }

    // ---------------- per-class atomics ----------------
    const int shard = bid & (NSHARD - 1);
    const int cq = tid * 4;
#pragma unroll
    for (int k = 0; k < 4; k++) {
        atomicAdd(&g_sA[shard][cq + k], A[k]);
        atomicAdd(&g_sC[shard][cq + k], cs[k]);
    }
    atomicAdd(&g_nU[shard][c], Un);
    atomicAdd(&g_nC[shard][c], cnf);

    // ---------------- block scalar reduce (all 8 warps) ----------------
    float nf = -nfp, sf = -sfp;
#pragma unroll
    for (int o = 16; o; o >>= 1) {
        Qs   += __shfl_down_sync(0xffffffffu, Qs,   o);
        Wn   += __shfl_down_sync(0xffffffffu, Wn,   o);
        hier += __shfl_down_sync(0xffffffffu, hier, o);
        nf   += __shfl_down_sync(0xffffffffu, nf,   o);
        sf   += __shfl_down_sync(0xffffffffu, sf,   o);
    }
    __shared__ float swm[5][8];
    if ((tid & 31) == 0) {
        int w = tid >> 5;
        swm[0][w] = Qs; swm[1][w] = Wn; swm[2][w] = hier; swm[3][w] = nf; swm[4][w] = sf;
    }
    __syncthreads();
    if (tid < 5) {
        float* pp = swm[tid];
        float vsum = pp[0] + pp[1] + pp[2] + pp[3] + pp[4] + pp[5] + pp[6] + pp[7];
        atomicAdd(&g_scl[tid], vsum);
    }

    // ---------------- last block finalizes and resets scratch ----------------
    __threadfence();
    __shared__ unsigned int s_last;
    if (tid == 0) s_last = (atomicAdd(&g_ctr, 1u) == (unsigned)(gridDim.x - 1)) ? 1u : 0u;
    __syncthreads();
    if (!s_last) return;
    __threadfence();

    double subAcc = 0.0, narrAcc = 0.0, valid = 0.0;
    for (int cc = tid; cc < NS; cc += BLOCK_MAIN) {
        float Av = g_sA[0][cc] + g_sA[1][cc] + g_sA[2][cc] + g_sA[3][cc];
        float Cv = g_sC[0][cc] + g_sC[1][cc] + g_sC[2][cc] + g_sC[3][cc];
        float pw = fminf(fmaxf((16384.0f - Cv) / (Cv + 1e-6f), 1.0f), 50.0f);
        subAcc += (double)pw * (double)Av;
    }
    for (int cc = tid; cc < NN; cc += BLOCK_MAIN) {
        float Uv = g_nU[0][cc] + g_nU[1][cc] + g_nU[2][cc] + g_nU[3][cc];
        float Cv = g_nC[0][cc] + g_nC[1][cc] + g_nC[2][cc] + g_nC[3][cc];
        float pw = fminf(fmaxf((16384.0f - Cv) / (Cv + 1e-6f), 1.0f), 50.0f);
        narrAcc += (double)pw * (double)Uv;
        valid   += (double)Cv;
    }
#pragma unroll
    for (int o = 16; o; o >>= 1) {
        subAcc  += __shfl_down_sync(0xffffffffu, subAcc,  o);
        narrAcc += __shfl_down_sync(0xffffffffu, narrAcc, o);
        valid   += __shfl_down_sync(0xffffffffu, valid,   o);
    }
    __shared__ double rd[24];
    if ((tid & 31) == 0) {
        int w = tid >> 5;   // 8 warps
        rd[w] = subAcc; rd[8 + w] = narrAcc; rd[16 + w] = valid;
    }
    __syncthreads();
    if (tid == 0) {
        double ss = 0.0, ns = 0.0, vv = 0.0;
        for (int i = 0; i < 8; i++) { ss += rd[i]; ns += rd[8 + i]; vv += rd[16 + i]; }
        double Qss = g_scl[0], Wns = g_scl[1];
        double hs = g_scl[2], nfs = g_scl[3], sfs = g_scl[4];

        double sub_total = ss + Qss;
        double narrative_loss = (ns + Wns) / (16384.0 * 128.0);
        double sub_loss = (vv > 0.0) ? (sub_total / 8.0) / fmax(vv, 1.0) : 0.0;
        double total = (narrative_loss - 0.1 * nfs / (16384.0 * 128.0))
                     + (sub_loss       - 0.1 * sfs / (16384.0 * 1024.0))
                     + 0.5 * hs / 16384.0;
        out[0] = (float)total;
    }
    __syncthreads();

    // reset scratch for the next graph replay
    for (int i = tid; i < NSHARD * NS; i += BLOCK_MAIN) {
        ((float*)g_sA)[i] = 0.f; ((float*)g_sC)[i] = 0.f;
    }
    for (int i = tid; i < NSHARD * NN; i += BLOCK_MAIN) {
        ((float*)g_nU)[i] = 0.f; ((float*)g_nC)[i] = 0.f;
    }
    if (tid < 8) g_scl[tid] = 0.f;
    if (tid == 0) g_ctr = 0u;
}

extern "C" void kernel_launch(void* const* d_in, const int* in_sizes, int n_in,
                              void* d_out, int out_size)
{
    const float* nlg = (const float*)d_in[0];   // narrative_logits [B,128]
    const float* slg = (const float*)d_in[1];   // subnarrative_logits [B,1024]
    const int*   nlb = (const int*)d_in[2];     // narrative_labels [B,128]
    const int*   slb = (const int*)d_in[3];     // subnarrative_labels [B,1024]
    (void)in_sizes; (void)n_in; (void)out_size;

    fused_kernel<<<GRID_MAIN, BLOCK_MAIN>>>(nlg, slg, nlb, slb, (float*)d_out);
}

// round 13
// speedup vs baseline: 1.0520x; 1.0520x over previous
#include <cuda_runtime.h>

#define B_ROWS 16384
#define NQUADS (B_ROWS / 4)      // 4096 row-quads
#define NN     128
#define NS     1024
#define GRID_MAIN 296            // 2 blocks/SM * 148 SMs
#define BLOCK_MAIN 256
#define NSHARD 4

#define C_LOG2E  1.4426950408889634f
#define C_LN2    0.6931471805599453f

// ---------------- scratch (device globals; statically zero-initialized) ----------------
// Invariant: zero at entry of every kernel_launch; finalizing block resets.
__device__ float g_sA[NSHARD][NS];   // sum g*s*softplus(-x)  (sub, pw-weighted part)
__device__ float g_sC[NSHARD][NS];   // sum s (ungated column count)
__device__ float g_nU[NSHARD][NN];   // sum y*softplus(-x)    (narrative)
__device__ float g_nC[NSHARD][NN];   // sum y
__device__ float g_scl[8];           // 0=Qs 1=Wn 2=hier 3=nf 4=sf
__device__ unsigned int g_ctr;

__device__ __forceinline__ float softplus_f(float x) {
    // softplus(x) = max(x,0) + log1p(exp(-|x|)); EX2 + LG2
    float e = exp2f(-C_LOG2E * fabsf(x));
    float L = __log2f(1.0f + e);
    return fmaxf(x, 0.0f) + C_LN2 * L;
}

__global__ __launch_bounds__(BLOCK_MAIN, 2)
void fused_kernel(const float* __restrict__ nlg, const float* __restrict__ slg,
                  const int* __restrict__ nlb,  const int* __restrict__ slb,
                  float* __restrict__ out)
{
    const int tid = threadIdx.x;
    const int bid = blockIdx.x;
    const int par = tid & 1;                 // 0: narrative rows {0,2}; 1: rows {1,3}
    const int c   = tid >> 1;                // narrative class for this thread

    float A[4]  = {0.f, 0.f, 0.f, 0.f};
    float cs[4] = {0.f, 0.f, 0.f, 0.f};
    float Un = 0.f, cnf = 0.f, Qs = 0.f, Wn = 0.f, hier = 0.f, nfp = 0.f, sfp = 0.f;

    // quad q -> rows (4q .. 4q+3); warp = 512B contiguous per vector load
    const float4* sp  = (const float4*)slg + (size_t)bid * 4 * (NS / 4) + tid;
    const int4*   slp = (const int4*)slb   + (size_t)bid * 4 * (NS / 4) + tid;
    const float*  np  = nlg + ((size_t)bid * 4 + par) * NN + c;   // rows par, par+2
    const int*    nbp = nlb + ((size_t)bid * 4 + par) * NN + c;
    const size_t  sstep = (size_t)GRID_MAIN * 4 * (NS / 4);
    const size_t  nstep = (size_t)GRID_MAIN * 4 * NN;
    const int     ROWQ = NS / 4;  // float4s per row

    // ---- prologue: load quad `bid` ----
    float4 v0 = __ldcs(sp),            v1 = __ldcs(sp + ROWQ);
    float4 v2 = __ldcs(sp + 2 * ROWQ), v3 = __ldcs(sp + 3 * ROWQ);
    int4   l0 = __ldcs(slp),            l1 = __ldcs(slp + ROWQ);
    int4   l2 = __ldcs(slp + 2 * ROWQ), l3 = __ldcs(slp + 3 * ROWQ);
    float  xn0 = __ldcs(np),  xn1 = __ldcs(np + 2 * NN);
    int    gi0 = __ldcs(nbp), gi1 = __ldcs(nbp + 2 * NN);

    for (int qd = bid; qd < NQUADS; qd += GRID_MAIN) {
        // ---- prefetch next quad, clamped-unconditional (last iter reloads current) ----
        const bool  more = (qd + GRID_MAIN) < NQUADS;
        const size_t sadv = more ? sstep : 0;
        const size_t nadv = more ? nstep : 0;
        sp += sadv; slp += sadv; np += nadv; nbp += nadv;
        float4 w0 = __ldcs(sp),            w1 = __ldcs(sp + ROWQ);
        float4 w2 = __ldcs(sp + 2 * ROWQ), w3 = __ldcs(sp + 3 * ROWQ);
        int4   m0 = __ldcs(slp),            m1 = __ldcs(slp + ROWQ);
        int4   m2 = __ldcs(slp + 2 * ROWQ), m3 = __ldcs(slp + 3 * ROWQ);
        float  yn0 = __ldcs(np),  yn1 = __ldcs(np + 2 * NN);
        int    hi0 = __ldcs(nbp), hi1 = __ldcs(nbp + 2 * NN);

        // ---- 2 narrative elements (own rows par, par+2) ----
        float g0 = (float)gi0, g1 = (float)gi1;
        float pn0, pn1;
        {
            float e0 = exp2f(-C_LOG2E * fabsf(xn0));
            float t0 = 1.0f + e0;
            float q0 = __fdividef(1.0f, t0);
            float spn0 = fmaxf(xn0, 0.0f) + C_LN2 * __log2f(t0);
            float spm0 = spn0 - xn0;
            bool  pos0 = (xn0 >= 0.0f);
            pn0 = pos0 ? q0 : e0 * q0;
            float om0 = pos0 ? e0 * q0 : q0;
            nfp = fmaf(g0 * om0 * om0, spm0, nfp);
            Un  = fmaf(g0, spm0, Un);
            Wn  = fmaf(1.0f - g0, spn0, Wn);

            float e1 = exp2f(-C_LOG2E * fabsf(xn1));
            float t1 = 1.0f + e1;
            float q1 = __fdividef(1.0f, t1);
            float spn1 = fmaxf(xn1, 0.0f) + C_LN2 * __log2f(t1);
            float spm1 = spn1 - xn1;
            bool  pos1 = (xn1 >= 0.0f);
            pn1 = pos1 ? q1 : e1 * q1;
            float om1 = pos1 ? e1 * q1 : q1;
            nfp = fmaf(g1 * om1 * om1, spm1, nfp);
            Un  = fmaf(g1, spm1, Un);
            Wn  = fmaf(1.0f - g1, spn1, Wn);
            cnf += g0 + g1;
        }

        // ---- exchange gates across the thread pair (packed, 1 shfl) ----
        int   pk   = gi0 | (gi1 << 1);
        int   pko  = __shfl_xor_sync(0xffffffffu, pk, 1);
        float og0  = (float)(pko & 1);
        float og1  = (float)((pko >> 1) & 1);
        float gr0 = par ? og0 : g0;
        float gr1 = par ? g0  : og0;
        float gr2 = par ? og1 : g1;
        float gr3 = par ? g1  : og1;

        // ---- 16 sub elements: 4 rows x 4 cols ----
        float xr[4][4] = { { v0.x, v0.y, v0.z, v0.w }, { v1.x, v1.y, v1.z, v1.w },
                           { v2.x, v2.y, v2.z, v2.w }, { v3.x, v3.y, v3.z, v3.w } };
        int   lr[4][4] = { { l0.x, l0.y, l0.z, l0.w }, { l1.x, l1.y, l1.z, l1.w },
                           { l2.x, l2.y, l2.z, l2.w }, { l3.x, l3.y, l3.z, l3.w } };
        float gr[4] = { gr0, gr1, gr2, gr3 };
        float mx[4];
#pragma unroll
        for (int rr = 0; rr < 4; rr++) {
            float m = xr[rr][0];
            float grr = gr[rr];
#pragma unroll
            for (int k = 0; k < 4; k++) {
                float x   = xr[rr][k];
                float s   = __int_as_float(lr[rr][k] * 0x3f800000);
                float spx = softplus_f(x);
                float spm = spx - x;
                float w   = exp2f(-2.0f * C_LOG2E * spx);
                sfp = fmaf(s * w, spm, sfp);
                float gs = grr * s;
                A[k] = fmaf(gs, spm, A[k]);
                Qs   = fmaf(grr - gs, spx, Qs);
                cs[k] += s;
                m = fmaxf(m, x);
            }
            mx[rr] = m;
        }

        // ---- hierarchy: full class max per row via pair shfl; own rows only ----
        float f0 = fmaxf(mx[0], __shfl_xor_sync(0xffffffffu, mx[0], 1));
        float f1 = fmaxf(mx[1], __shfl_xor_sync(0xffffffffu, mx[1], 1));
        float f2 = fmaxf(mx[2], __shfl_xor_sync(0xffffffffu, mx[2], 1));
        float f3 = fmaxf(mx[3], __shfl_xor_sync(0xffffffffu, mx[3], 1));
        float fa = par ? f1 : f0;
        float fb = par ? f3 : f2;
        {
            float ea = exp2f(-C_LOG2E * fa);
            float pa = __fdividef(1.0f, 1.0f + ea);
            hier = fmaf(g0, fmaxf(pa - pn0, 0.0f), hier);
            float eb = exp2f(-C_LOG2E * fb);
            float pb = __fdividef(1.0f, 1.0f + eb);
            hier = fmaf(g1, fmaxf(pb - pn1, 0.0f), hier);
        }

        // rotate double-buffer
        v0 = w0; v1 = w1; v2 = w2; v3 = w3;
        l0 = m0; l1 = m1; l2 = m2; l3 = m3;
        xn0 = yn0; xn1 = yn1; gi0 = hi0; gi1 = hi1;
    }

    // ---------------- per-class atomics ----------------
    const int shard = bid & (NSHARD - 1);
    const int cq = tid * 4;
#pragma unroll
    for (int k = 0; k < 4; k++) {
        atomicAdd(&g_sA[shard][cq + k], A[k]);
        atomicAdd(&g_sC[shard][cq + k], cs[k]);
    }
    atomicAdd(&g_nU[shard][c], Un);
    atomicAdd(&g_nC[shard][c], cnf);

    // ---------------- block scalar reduce (all 8 warps) ----------------
    float nf = -nfp, sf = -sfp;
#pragma unroll
    for (int o = 16; o; o >>= 1) {
        Qs   += __shfl_down_sync(0xffffffffu, Qs,   o);
        Wn   += __shfl_down_sync(0xffffffffu, Wn,   o);
        hier += __shfl_down_sync(0xffffffffu, hier, o);
        nf   += __shfl_down_sync(0xffffffffu, nf,   o);
        sf   += __shfl_down_sync(0xffffffffu, sf,   o);
    }
    __shared__ float swm[5][8];
    if ((tid & 31) == 0) {
        int w = tid >> 5;
        swm[0][w] = Qs; swm[1][w] = Wn; swm[2][w] = hier; swm[3][w] = nf; swm[4][w] = sf;
    }
    __syncthreads();
    if (tid < 5) {
        float* pp = swm[tid];
        float vsum = pp[0] + pp[1] + pp[2] + pp[3] + pp[4] + pp[5] + pp[6] + pp[7];
        atomicAdd(&g_scl[tid], vsum);
    }

    // ---------------- last block finalizes and resets scratch ----------------
    __threadfence();
    __shared__ unsigned int s_last;
    if (tid == 0) s_last = (atomicAdd(&g_ctr, 1u) == (unsigned)(gridDim.x - 1)) ? 1u : 0u;
    __syncthreads();
    if (!s_last) return;
    __threadfence();

    double subAcc = 0.0, narrAcc = 0.0, valid = 0.0;
    for (int cc = tid; cc < NS; cc += BLOCK_MAIN) {
        float Av = g_sA[0][cc] + g_sA[1][cc] + g_sA[2][cc] + g_sA[3][cc];
        float Cv = g_sC[0][cc] + g_sC[1][cc] + g_sC[2][cc] + g_sC[3][cc];
        float pw = fminf(fmaxf((16384.0f - Cv) / (Cv + 1e-6f), 1.0f), 50.0f);
        subAcc += (double)pw * (double)Av;
    }
    for (int cc = tid; cc < NN; cc += BLOCK_MAIN) {
        float Uv = g_nU[0][cc] + g_nU[1][cc] + g_nU[2][cc] + g_nU[3][cc];
        float Cv = g_nC[0][cc] + g_nC[1][cc] + g_nC[2][cc] + g_nC[3][cc];
        float pw = fminf(fmaxf((16384.0f - Cv) / (Cv + 1e-6f), 1.0f), 50.0f);
        narrAcc += (double)pw * (double)Uv;
        valid   += (double)Cv;
    }
#pragma unroll
    for (int o = 16; o; o >>= 1) {
        subAcc  += __shfl_down_sync(0xffffffffu, subAcc,  o);
        narrAcc += __shfl_down_sync(0xffffffffu, narrAcc, o);
        valid   += __shfl_down_sync(0xffffffffu, valid,   o);
    }
    __shared__ double rd[24];
    if ((tid & 31) == 0) {
        int w = tid >> 5;   // 8 warps
        rd[w] = subAcc; rd[8 + w] = narrAcc; rd[16 + w] = valid;
    }
    __syncthreads();
    if (tid == 0) {
        double ss = 0.0, ns = 0.0, vv = 0.0;
        for (int i = 0; i < 8; i++) { ss += rd[i]; ns += rd[8 + i]; vv += rd[16 + i]; }
        double Qss = g_scl[0], Wns = g_scl[1];
        double hs = g_scl[2], nfs = g_scl[3], sfs = g_scl[4];

        double sub_total = ss + Qss;
        double narrative_loss = (ns + Wns) / (16384.0 * 128.0);
        double sub_loss = (vv > 0.0) ? (sub_total / 8.0) / fmax(vv, 1.0) : 0.0;
        double total = (narrative_loss - 0.1 * nfs / (16384.0 * 128.0))
                     + (sub_loss       - 0.1 * sfs / (16384.0 * 1024.0))
                     + 0.5 * hs / 16384.0;
        out[0] = (float)total;
    }
    __syncthreads();

    // reset scratch for the next graph replay
    for (int i = tid; i < NSHARD * NS; i += BLOCK_MAIN) {
        ((float*)g_sA)[i] = 0.f; ((float*)g_sC)[i] = 0.f;
    }
    for (int i = tid; i < NSHARD * NN; i += BLOCK_MAIN) {
        ((float*)g_nU)[i] = 0.f; ((float*)g_nC)[i] = 0.f;
    }
    if (tid < 8) g_scl[tid] = 0.f;
    if (tid == 0) g_ctr = 0u;
}

extern "C" void kernel_launch(void* const* d_in, const int* in_sizes, int n_in,
                              void* d_out, int out_size)
{
    const float* nlg = (const float*)d_in[0];   // narrative_logits [B,128]
    const float* slg = (const float*)d_in[1];   // subnarrative_logits [B,1024]
    const int*   nlb = (const int*)d_in[2];     // narrative_labels [B,128]
    const int*   slb = (const int*)d_in[3];     // subnarrative_labels [B,1024]
    (void)in_sizes; (void)n_in; (void)out_size;

    fused_kernel<<<GRID_MAIN, BLOCK_MAIN>>>(nlg, slg, nlb, slb, (float*)d_out);
}